// round 1
// baseline (speedup 1.0000x reference)
#include <cuda_runtime.h>
#include <math.h>

#define N_CAMS 5
#define Bn 4
#define Jn 15
#define Hn 128
#define Wn 240
#define CX 80
#define CY 80
#define CZ 20
#define NBINS (CX*CY*CZ)        // 128000
#define HW (Hn*Wn)              // 30720
#define THREADS 256
#define BLOCKS_PER_B (NBINS/THREADS)  // 500
#define EPSV 1e-6f

__global__ __launch_bounds__(THREADS) void project_kernel(
    const float* __restrict__ heat,   // (5,4,15,128,240)
    const float* __restrict__ Rm,     // (5,4,3,3)
    const float* __restrict__ Tm,     // (5,4,3)
    const float* __restrict__ fm,     // (5,4,2)
    const float* __restrict__ cm,     // (5,4,2)
    const float* __restrict__ km,     // (5,4,3)
    const float* __restrict__ pm,     // (5,4,2)
    const float* __restrict__ whm,    // (5,4,2)
    const float* __restrict__ gc,     // (4,3)
    const float* __restrict__ gs,     // (3,)
    float* __restrict__ cubes,        // (4,15,128000)
    float* __restrict__ grids)        // (4,128000,3)
{
    __shared__ float s[N_CAMS * 23];

    const int b = blockIdx.x / BLOCKS_PER_B;
    const int m = (blockIdx.x % BLOCKS_PER_B) * THREADS + threadIdx.x;

    // Stage camera params for this batch into shared: per cam 23 floats:
    // R[0..8], T[9..11], f[12..13], c[14..15], k[16..18], p[19..20], wh[21..22]
    for (int i = threadIdx.x; i < N_CAMS * 23; i += THREADS) {
        const int n = i / 23, q = i % 23;
        const int nb = n * Bn + b;
        float v;
        if      (q < 9)  v = Rm [nb*9 + q];
        else if (q < 12) v = Tm [nb*3 + (q-9)];
        else if (q < 14) v = fm [nb*2 + (q-12)];
        else if (q < 16) v = cm [nb*2 + (q-14)];
        else if (q < 19) v = km [nb*3 + (q-16)];
        else if (q < 21) v = pm [nb*2 + (q-19)];
        else             v = whm[nb*2 + (q-21)];
        s[i] = v;
    }
    __syncthreads();

    // Voxel coordinates: m = (ix*CY + iy)*CZ + iz (x slowest, z fastest)
    const int ixg = m / (CY * CZ);
    const int iyg = (m / CZ) % CY;
    const int izg = m % CZ;
    const float gs0 = gs[0], gs1 = gs[1], gs2 = gs[2];
    const float gx = -0.5f*gs0 + (float)ixg * (gs0 / (float)(CX-1)) + gc[b*3+0];
    const float gy = -0.5f*gs1 + (float)iyg * (gs1 / (float)(CY-1)) + gc[b*3+1];
    const float gz = -0.5f*gs2 + (float)izg * (gs2 / (float)(CZ-1)) + gc[b*3+2];

    // Write grids output
    grids[((long)b*NBINS + m)*3 + 0] = gx;
    grids[((long)b*NBINS + m)*3 + 1] = gy;
    grids[((long)b*NBINS + m)*3 + 2] = gz;

    float den = EPSV;
    float w[N_CAMS][4];
    int   idx[N_CAMS][4];   // absolute index into heat for joint 0

    #pragma unroll
    for (int n = 0; n < N_CAMS; n++) {
        const float* cp = s + n*23;
        const float dx = gx - cp[9], dy = gy - cp[10], dz = gz - cp[11];
        const float xc0 = cp[0]*dx + cp[1]*dy + cp[2]*dz;
        const float xc1 = cp[3]*dx + cp[4]*dy + cp[5]*dz;
        const float xc2 = cp[6]*dx + cp[7]*dy + cp[8]*dz;
        const float inv = 1.0f / xc2;
        const float y0 = xc0 * inv, y1 = xc1 * inv;
        const float r2 = y0*y0 + y1*y1;
        const float radial = 1.0f + cp[16]*r2 + cp[17]*r2*r2 + cp[18]*r2*r2*r2;
        const float tanp = cp[19]*y1 + cp[20]*y0;
        const float rt = radial + tanp;
        const float xy0 = y0*rt + r2*cp[20];
        const float xy1 = y1*rt + r2*cp[19];
        const float px = xy0*cp[12] + cp[14];
        const float py = xy1*cp[13] + cp[15];
        const float wv = cp[21], hv = cp[22];
        const float bound = (px >= 0.0f && py >= 0.0f && px < wv && py < hv) ? 1.0f : 0.0f;
        den += bound;
        const float mwh = fmaxf(wv, hv);
        float pxc = fminf(fmaxf(px, -1.0f), mwh);
        float pyc = fminf(fmaxf(py, -1.0f), mwh);
        float nx = pxc / (wv - 1.0f) * 2.0f - 1.0f;
        float ny = pyc / (hv - 1.0f) * 2.0f - 1.0f;
        nx = fminf(fmaxf(nx, -1.1f), 1.1f);
        ny = fminf(fmaxf(ny, -1.1f), 1.1f);
        const float fx = (nx + 1.0f) * 0.5f * (float)(Wn - 1);
        const float fy = (ny + 1.0f) * 0.5f * (float)(Hn - 1);
        const float x0 = floorf(fx), yy0 = floorf(fy);
        const float x1 = x0 + 1.0f, yy1 = yy0 + 1.0f;
        const float wx1 = fx - x0, wx0 = 1.0f - wx1;
        const float wy1 = fy - yy0, wy0 = 1.0f - wy1;
        // corner validity in float domain (matches reference)
        const float vx0 = (x0 >= 0.0f && x0 < (float)Wn) ? 1.0f : 0.0f;
        const float vx1 = (x1 >= 0.0f && x1 < (float)Wn) ? 1.0f : 0.0f;
        const float vy0 = (yy0 >= 0.0f && yy0 < (float)Hn) ? 1.0f : 0.0f;
        const float vy1 = (yy1 >= 0.0f && yy1 < (float)Hn) ? 1.0f : 0.0f;
        const int xc0i = min(max((int)x0, 0), Wn-1);
        const int xc1i = min(max((int)x1, 0), Wn-1);
        const int yc0i = min(max((int)yy0, 0), Hn-1);
        const int yc1i = min(max((int)yy1, 0), Hn-1);
        const int base = (n*Bn + b) * Jn * HW;   // joint 0 plane
        idx[n][0] = base + yc0i*Wn + xc0i;
        idx[n][1] = base + yc0i*Wn + xc1i;
        idx[n][2] = base + yc1i*Wn + xc0i;
        idx[n][3] = base + yc1i*Wn + xc1i;
        w[n][0] = wx0*wy0*vx0*vy0*bound;
        w[n][1] = wx1*wy0*vx1*vy0*bound;
        w[n][2] = wx0*wy1*vx0*vy1*bound;
        w[n][3] = wx1*wy1*vx1*vy1*bound;
    }

    const float invden = 1.0f / den;

    #pragma unroll
    for (int j = 0; j < Jn; j++) {
        float acc = 0.0f;
        const int joff = j * HW;
        #pragma unroll
        for (int n = 0; n < N_CAMS; n++) {
            acc += w[n][0] * __ldg(&heat[idx[n][0] + joff]);
            acc += w[n][1] * __ldg(&heat[idx[n][1] + joff]);
            acc += w[n][2] * __ldg(&heat[idx[n][2] + joff]);
            acc += w[n][3] * __ldg(&heat[idx[n][3] + joff]);
        }
        float v = acc * invden;
        v = fminf(fmaxf(v, 0.0f), 1.0f);
        cubes[((long)b*Jn + j)*NBINS + m] = v;
    }
}

extern "C" void kernel_launch(void* const* d_in, const int* in_sizes, int n_in,
                              void* d_out, int out_size) {
    const float* heat = (const float*)d_in[0];
    const float* Rm   = (const float*)d_in[1];
    const float* Tm   = (const float*)d_in[2];
    const float* fm   = (const float*)d_in[3];
    const float* cm   = (const float*)d_in[4];
    const float* km   = (const float*)d_in[5];
    const float* pm   = (const float*)d_in[6];
    const float* whm  = (const float*)d_in[7];
    const float* gc   = (const float*)d_in[8];
    const float* gs   = (const float*)d_in[9];

    float* cubes = (float*)d_out;
    float* grids = cubes + (long)Bn * Jn * NBINS;   // tuple output: cubes then grids

    dim3 grid(Bn * BLOCKS_PER_B);
    project_kernel<<<grid, THREADS>>>(heat, Rm, Tm, fm, cm, km, pm, whm, gc, gs,
                                      cubes, grids);
}